// round 1
// baseline (speedup 1.0000x reference)
#include <cuda_runtime.h>
#include <cstdint>

#define N_USERS 200000
#define N_SPOTS 50000
#define N_NODES (N_USERS + N_SPOTS)
#define N_EDGES 3200000
#define D 64
#define D4 (D / 4)   // 16 float4 per row

// Scratch (no allocations allowed): combined degree + inv-sqrt arrays.
// Node index space: [0, N_USERS) = users, [N_USERS, N_NODES) = spots.
__device__ int   g_deg[N_NODES];
__device__ float g_isq[N_NODES];

__global__ void __launch_bounds__(256) zero_deg_kernel() {
    int i = blockIdx.x * blockDim.x + threadIdx.x;
    if (i < N_NODES) g_deg[i] = 0;
}

__global__ void __launch_bounds__(256) degree_kernel(const int* __restrict__ user_idx,
                                                     const int* __restrict__ spot_idx) {
    int e = blockIdx.x * blockDim.x + threadIdx.x;
    if (e < N_EDGES) {
        atomicAdd(&g_deg[user_idx[e]], 1);
        atomicAdd(&g_deg[N_USERS + spot_idx[e]], 1);
    }
}

__global__ void __launch_bounds__(256) isq_kernel() {
    int i = blockIdx.x * blockDim.x + threadIdx.x;
    if (i < N_NODES) {
        float d = (float)g_deg[i];
        g_isq[i] = rsqrtf(d == 0.0f ? 1e-6f : d);
    }
}

// 16 threads per edge; each thread handles one float4 chunk (4 columns) of
// BOTH directions: spot->user and user->spot. Atomic adds (no return value ->
// REDG) to 4 consecutive fp32 addresses.
__global__ void __launch_bounds__(256) scatter_kernel(const float* __restrict__ user_x,
                                                      const float* __restrict__ spot_x,
                                                      const int* __restrict__ user_idx,
                                                      const int* __restrict__ spot_idx,
                                                      float* __restrict__ out) {
    long long t = (long long)blockIdx.x * blockDim.x + threadIdx.x;
    int e = (int)(t >> 4);
    int lane = (int)(t & 15);
    if (e >= N_EDGES) return;

    int u = user_idx[e];   // broadcast within the 16-thread group (same address)
    int s = spot_idx[e];

    float isq_u = g_isq[u];
    float isq_s = g_isq[N_USERS + s];

    const float4* sx4 = (const float4*)spot_x;
    const float4* ux4 = (const float4*)user_x;

    float4 sv = sx4[(long long)s * D4 + lane];
    float4 uv = ux4[(long long)u * D4 + lane];

    float* user_out = out;                                   // rows [0, N_USERS)
    float* spot_out = out + (long long)N_USERS * D;          // rows [0, N_SPOTS)

    float* du = user_out + (long long)u * D + lane * 4;
    atomicAdd(du + 0, sv.x * isq_s);
    atomicAdd(du + 1, sv.y * isq_s);
    atomicAdd(du + 2, sv.z * isq_s);
    atomicAdd(du + 3, sv.w * isq_s);

    float* ds = spot_out + (long long)s * D + lane * 4;
    atomicAdd(ds + 0, uv.x * isq_u);
    atomicAdd(ds + 1, uv.y * isq_u);
    atomicAdd(ds + 2, uv.z * isq_u);
    atomicAdd(ds + 3, uv.w * isq_u);
}

// Post-scale: out row layout is [user rows][spot rows], which matches the
// combined g_isq index space exactly: node = element_index / 64.
__global__ void __launch_bounds__(256) scale_kernel(float* __restrict__ out) {
    long long i = ((long long)blockIdx.x * blockDim.x + threadIdx.x) * 4;
    const long long total = (long long)N_NODES * D;
    if (i >= total) return;
    int node = (int)(i >> 6);
    float isq = g_isq[node];
    float4* p = (float4*)(out + i);
    float4 v = *p;
    v.x *= isq; v.y *= isq; v.z *= isq; v.w *= isq;
    *p = v;
}

extern "C" void kernel_launch(void* const* d_in, const int* in_sizes, int n_in,
                              void* d_out, int out_size) {
    const float* user_x   = (const float*)d_in[0];
    const float* spot_x   = (const float*)d_in[1];
    const int*   user_idx = (const int*)d_in[2];
    const int*   spot_idx = (const int*)d_in[3];
    float* out = (float*)d_out;

    // Zero the output accumulator (poisoned to 0xAA by the harness).
    cudaMemsetAsync(d_out, 0, (size_t)out_size * sizeof(float), 0);

    zero_deg_kernel<<<(N_NODES + 255) / 256, 256>>>();
    degree_kernel<<<(N_EDGES + 255) / 256, 256>>>(user_idx, spot_idx);
    isq_kernel<<<(N_NODES + 255) / 256, 256>>>();

    long long scatter_threads = (long long)N_EDGES * 16;
    int scatter_blocks = (int)((scatter_threads + 255) / 256);
    scatter_kernel<<<scatter_blocks, 256>>>(user_x, spot_x, user_idx, spot_idx, out);

    long long total = (long long)N_NODES * D;
    int scale_blocks = (int)((total / 4 + 255) / 256);
    scale_kernel<<<scale_blocks, 256>>>(out);
}

// round 2
// speedup vs baseline: 2.5266x; 2.5266x over previous
#include <cuda_runtime.h>
#include <cstdint>

#define N_USERS 200000
#define N_SPOTS 50000
#define N_NODES (N_USERS + N_SPOTS)
#define N_EDGES 3200000
#define D 64
#define D4 (D / 4)   // 16 float4 per row

// Scratch (no allocations allowed): combined degree + inv-sqrt arrays.
// Node index space: [0, N_USERS) = users, [N_USERS, N_NODES) = spots.
__device__ int   g_deg[N_NODES];
__device__ float g_isq[N_NODES];

__global__ void __launch_bounds__(256) zero_deg_kernel() {
    int i = blockIdx.x * blockDim.x + threadIdx.x;
    if (i < N_NODES) g_deg[i] = 0;
}

__global__ void __launch_bounds__(256) degree_kernel(const int* __restrict__ user_idx,
                                                     const int* __restrict__ spot_idx) {
    int e = blockIdx.x * blockDim.x + threadIdx.x;
    if (e < N_EDGES) {
        atomicAdd(&g_deg[user_idx[e]], 1);
        atomicAdd(&g_deg[N_USERS + spot_idx[e]], 1);
    }
}

__global__ void __launch_bounds__(256) isq_kernel() {
    int i = blockIdx.x * blockDim.x + threadIdx.x;
    if (i < N_NODES) {
        float d = (float)g_deg[i];
        g_isq[i] = rsqrtf(d == 0.0f ? 1e-6f : d);
    }
}

__device__ __forceinline__ void red_add_v4(float* addr, float a, float b, float c, float d) {
    asm volatile("red.global.add.v4.f32 [%0], {%1, %2, %3, %4};"
                 :: "l"(addr), "f"(a), "f"(b), "f"(c), "f"(d)
                 : "memory");
}

// 16 threads per edge; each thread handles one float4 chunk (4 columns) of
// BOTH directions. Vectorized red.global.add.v4.f32 — one atomic instruction
// per 16B instead of four scalar REDs.
__global__ void __launch_bounds__(256) scatter_kernel(const float* __restrict__ user_x,
                                                      const float* __restrict__ spot_x,
                                                      const int* __restrict__ user_idx,
                                                      const int* __restrict__ spot_idx,
                                                      float* __restrict__ out) {
    long long t = (long long)blockIdx.x * blockDim.x + threadIdx.x;
    int e = (int)(t >> 4);
    int lane = (int)(t & 15);
    if (e >= N_EDGES) return;

    int u = user_idx[e];   // broadcast within the 16-thread group
    int s = spot_idx[e];

    float isq_u = g_isq[u];
    float isq_s = g_isq[N_USERS + s];

    const float4* sx4 = (const float4*)spot_x;
    const float4* ux4 = (const float4*)user_x;

    float4 sv = sx4[(long long)s * D4 + lane];
    float4 uv = ux4[(long long)u * D4 + lane];

    float* user_out = out;                                   // rows [0, N_USERS)
    float* spot_out = out + (long long)N_USERS * D;          // rows [0, N_SPOTS)

    float* du = user_out + (long long)u * D + lane * 4;
    red_add_v4(du, sv.x * isq_s, sv.y * isq_s, sv.z * isq_s, sv.w * isq_s);

    float* ds = spot_out + (long long)s * D + lane * 4;
    red_add_v4(ds, uv.x * isq_u, uv.y * isq_u, uv.z * isq_u, uv.w * isq_u);
}

// Post-scale: out row layout is [user rows][spot rows], matching the combined
// g_isq index space exactly: node = element_index / 64.
__global__ void __launch_bounds__(256) scale_kernel(float* __restrict__ out) {
    long long i = ((long long)blockIdx.x * blockDim.x + threadIdx.x) * 4;
    const long long total = (long long)N_NODES * D;
    if (i >= total) return;
    int node = (int)(i >> 6);
    float isq = g_isq[node];
    float4* p = (float4*)(out + i);
    float4 v = *p;
    v.x *= isq; v.y *= isq; v.z *= isq; v.w *= isq;
    *p = v;
}

extern "C" void kernel_launch(void* const* d_in, const int* in_sizes, int n_in,
                              void* d_out, int out_size) {
    const float* user_x   = (const float*)d_in[0];
    const float* spot_x   = (const float*)d_in[1];
    const int*   user_idx = (const int*)d_in[2];
    const int*   spot_idx = (const int*)d_in[3];
    float* out = (float*)d_out;

    cudaMemsetAsync(d_out, 0, (size_t)out_size * sizeof(float), 0);

    zero_deg_kernel<<<(N_NODES + 255) / 256, 256>>>();
    degree_kernel<<<(N_EDGES + 255) / 256, 256>>>(user_idx, spot_idx);
    isq_kernel<<<(N_NODES + 255) / 256, 256>>>();

    long long scatter_threads = (long long)N_EDGES * 16;
    int scatter_blocks = (int)((scatter_threads + 255) / 256);
    scatter_kernel<<<scatter_blocks, 256>>>(user_x, spot_x, user_idx, spot_idx, out);

    long long total = (long long)N_NODES * D;
    int scale_blocks = (int)((total / 4 + 255) / 256);
    scale_kernel<<<scale_blocks, 256>>>(out);
}